// round 3
// baseline (speedup 1.0000x reference)
#include <cuda_runtime.h>
#include <cuda_bf16.h>
#include <math.h>

// Problem constants
#define Bc 2
#define Lc 2048
#define Dc 1024
#define Hc 16
#define Dhc 64
#define Mg (Bc*Lc)          // 4096 rows
#define Ng (Hc*Dhc)         // 1024 cols per projection

// Scratch (B*H*L*Dh = 4M floats = 16MB each)
__device__ float g_q[(size_t)Bc*Hc*Lc*Dhc];
__device__ float g_k[(size_t)Bc*Hc*Lc*Dhc];
__device__ float g_v[(size_t)Bc*Hc*Lc*Dhc];
__device__ float g_o[(size_t)Bc*Lc*Dc];

// ---------------------------------------------------------------------------
// 128x128x8 SGEMM, 256 threads, 8x8 per thread.
// A: [M,1024] row-major (x or o). B: [1024,1024] row-major (W flattened).
// ---------------------------------------------------------------------------
__global__ __launch_bounds__(256, 2)
void qkv_kernel(const float* __restrict__ x,
                const float* __restrict__ Wq,
                const float* __restrict__ Wk,
                const float* __restrict__ Wv)
{
    __shared__ float AsT[8][132];
    __shared__ float Bs[8][128];

    const int tid = threadIdx.x;
    const int ty = tid >> 4, tx = tid & 15;
    const int m0 = blockIdx.x * 128;
    const int n0 = blockIdx.y * 128;

    const float* W = (blockIdx.z == 0) ? Wq : (blockIdx.z == 1) ? Wk : Wv;
    float* outp   = (blockIdx.z == 0) ? g_q : (blockIdx.z == 1) ? g_k : g_v;

    const int a_row = tid >> 1;           // 0..127
    const int a_k4  = (tid & 1) * 4;      // 0 or 4
    const int b_k   = tid >> 5;           // 0..7
    const int b_c4  = (tid & 31) * 4;     // 0..124

    const float* Aptr = x + (size_t)(m0 + a_row) * Dc + a_k4;
    const float* Bptr = W + (size_t)b_k * Ng + n0 + b_c4;

    float acc[8][8];
#pragma unroll
    for (int i = 0; i < 8; i++)
#pragma unroll
        for (int j = 0; j < 8; j++) acc[i][j] = 0.f;

    for (int k0 = 0; k0 < Dc; k0 += 8) {
        float4 av = *(const float4*)(Aptr + k0);
        float4 bv = *(const float4*)(Bptr + (size_t)k0 * Ng);
        AsT[a_k4 + 0][a_row] = av.x;
        AsT[a_k4 + 1][a_row] = av.y;
        AsT[a_k4 + 2][a_row] = av.z;
        AsT[a_k4 + 3][a_row] = av.w;
        *(float4*)&Bs[b_k][b_c4] = bv;
        __syncthreads();

#pragma unroll
        for (int kk = 0; kk < 8; kk++) {
            float4 a0 = *(const float4*)&AsT[kk][ty * 8];
            float4 a1 = *(const float4*)&AsT[kk][ty * 8 + 4];
            float4 b0 = *(const float4*)&Bs[kk][tx * 8];
            float4 b1 = *(const float4*)&Bs[kk][tx * 8 + 4];
            float a[8] = {a0.x, a0.y, a0.z, a0.w, a1.x, a1.y, a1.z, a1.w};
            float b[8] = {b0.x, b0.y, b0.z, b0.w, b1.x, b1.y, b1.z, b1.w};
#pragma unroll
            for (int i = 0; i < 8; i++)
#pragma unroll
                for (int j = 0; j < 8; j++)
                    acc[i][j] += a[i] * b[j];
        }
        __syncthreads();
    }

    // Epilogue: scatter to [b][h][l][e] layout
    const int n_base = n0 + tx * 8;
    const int h = n_base >> 6;
    const int e0 = n_base & 63;
#pragma unroll
    for (int i = 0; i < 8; i++) {
        const int m = m0 + ty * 8 + i;
        const int bb = m >> 11;
        const int l = m & 2047;
        size_t off = (((size_t)(bb * Hc + h) * Lc + l) << 6) + e0;
        *(float4*)&outp[off]     = make_float4(acc[i][0], acc[i][1], acc[i][2], acc[i][3]);
        *(float4*)&outp[off + 4] = make_float4(acc[i][4], acc[i][5], acc[i][6], acc[i][7]);
    }
}

__global__ __launch_bounds__(256, 2)
void out_kernel(const float* __restrict__ Wout, float* __restrict__ out)
{
    __shared__ float AsT[8][132];
    __shared__ float Bs[8][128];

    const int tid = threadIdx.x;
    const int ty = tid >> 4, tx = tid & 15;
    const int m0 = blockIdx.x * 128;
    const int n0 = blockIdx.y * 128;

    const int a_row = tid >> 1;
    const int a_k4  = (tid & 1) * 4;
    const int b_k   = tid >> 5;
    const int b_c4  = (tid & 31) * 4;

    const float* Aptr = g_o + (size_t)(m0 + a_row) * Dc + a_k4;
    const float* Bptr = Wout + (size_t)b_k * Dc + n0 + b_c4;

    float acc[8][8];
#pragma unroll
    for (int i = 0; i < 8; i++)
#pragma unroll
        for (int j = 0; j < 8; j++) acc[i][j] = 0.f;

    for (int k0 = 0; k0 < Dc; k0 += 8) {
        float4 av = *(const float4*)(Aptr + k0);
        float4 bv = *(const float4*)(Bptr + (size_t)k0 * Dc);
        AsT[a_k4 + 0][a_row] = av.x;
        AsT[a_k4 + 1][a_row] = av.y;
        AsT[a_k4 + 2][a_row] = av.z;
        AsT[a_k4 + 3][a_row] = av.w;
        *(float4*)&Bs[b_k][b_c4] = bv;
        __syncthreads();

#pragma unroll
        for (int kk = 0; kk < 8; kk++) {
            float4 a0 = *(const float4*)&AsT[kk][ty * 8];
            float4 a1 = *(const float4*)&AsT[kk][ty * 8 + 4];
            float4 b0 = *(const float4*)&Bs[kk][tx * 8];
            float4 b1 = *(const float4*)&Bs[kk][tx * 8 + 4];
            float a[8] = {a0.x, a0.y, a0.z, a0.w, a1.x, a1.y, a1.z, a1.w};
            float b[8] = {b0.x, b0.y, b0.z, b0.w, b1.x, b1.y, b1.z, b1.w};
#pragma unroll
            for (int i = 0; i < 8; i++)
#pragma unroll
                for (int j = 0; j < 8; j++)
                    acc[i][j] += a[i] * b[j];
        }
        __syncthreads();
    }

#pragma unroll
    for (int i = 0; i < 8; i++) {
        const int m = m0 + ty * 8 + i;
        size_t off = (size_t)m * Dc + n0 + tx * 8;
        *(float4*)&out[off]     = make_float4(acc[i][0], acc[i][1], acc[i][2], acc[i][3]);
        *(float4*)&out[off + 4] = make_float4(acc[i][4], acc[i][5], acc[i][6], acc[i][7]);
    }
}

// ---------------------------------------------------------------------------
// Causal flash attention. Tile 64x64, 256 threads, 4x4 per thread with
// strided column/row mapping (r = ty+16i, c = tx+16j) -> conflict-free LDS
// with 65-float row stride.
// ---------------------------------------------------------------------------
#define FL_SMEM (4 * 64 * 65 * 4)

__global__ __launch_bounds__(256, 3)
void flash_kernel()
{
    extern __shared__ float smem[];
    float* Qs = smem;
    float* Ks = smem + 64 * 65;
    float* Vs = smem + 2 * 64 * 65;
    float* Ps = smem + 3 * 64 * 65;
#define QS(r,c) Qs[(r)*65+(c)]
#define KS(r,c) Ks[(r)*65+(c)]
#define VS(r,c) Vs[(r)*65+(c)]
#define PS(r,c) Ps[(r)*65+(c)]

    const int qt = gridDim.x - 1 - blockIdx.x;  // heavy tiles first
    const int bh = blockIdx.y;
    const int tid = threadIdx.x;
    const int ty = tid >> 4, tx = tid & 15;

    const float* qb = g_q + (size_t)bh * Lc * Dhc;
    const float* kb = g_k + (size_t)bh * Lc * Dhc;
    const float* vb = g_v + (size_t)bh * Lc * Dhc;

    // Load Q tile
    for (int i = tid; i < 64 * 64; i += 256) {
        int r = i >> 6, e = i & 63;
        QS(r, e) = qb[(size_t)(qt * 64 + r) * 64 + e];
    }

    float m_i[4], l_i[4], O[4][4];
#pragma unroll
    for (int i = 0; i < 4; i++) {
        m_i[i] = -3.0e38f;
        l_i[i] = 0.f;
#pragma unroll
        for (int j = 0; j < 4; j++) O[i][j] = 0.f;
    }

    for (int kt = 0; kt <= qt; kt++) {
        // Load K,V tiles
        for (int i = tid; i < 64 * 64; i += 256) {
            int r = i >> 6, e = i & 63;
            KS(r, e) = kb[(size_t)(kt * 64 + r) * 64 + e];
            VS(r, e) = vb[(size_t)(kt * 64 + r) * 64 + e];
        }
        __syncthreads();

        // Phase 1: S = Q K^T
        float s[4][4];
#pragma unroll
        for (int i = 0; i < 4; i++)
#pragma unroll
            for (int j = 0; j < 4; j++) s[i][j] = 0.f;

#pragma unroll 8
        for (int e = 0; e < 64; e++) {
            float a[4], b[4];
#pragma unroll
            for (int i = 0; i < 4; i++) a[i] = QS(ty + 16 * i, e);
#pragma unroll
            for (int j = 0; j < 4; j++) b[j] = KS(tx + 16 * j, e);
#pragma unroll
            for (int i = 0; i < 4; i++)
#pragma unroll
                for (int j = 0; j < 4; j++)
                    s[i][j] += a[i] * b[j];
        }

        // Scale + causal mask (only diagonal tile needs mask)
        const float sc = 0.125f;  // 1/sqrt(64)
        if (kt == qt) {
#pragma unroll
            for (int i = 0; i < 4; i++)
#pragma unroll
                for (int j = 0; j < 4; j++)
                    s[i][j] = (tx + 16 * j > ty + 16 * i) ? -3.0e38f : s[i][j] * sc;
        } else {
#pragma unroll
            for (int i = 0; i < 4; i++)
#pragma unroll
                for (int j = 0; j < 4; j++)
                    s[i][j] *= sc;
        }

        // Online softmax (per row group of 16 tx lanes)
#pragma unroll
        for (int i = 0; i < 4; i++) {
            float rmax = fmaxf(fmaxf(s[i][0], s[i][1]), fmaxf(s[i][2], s[i][3]));
#pragma unroll
            for (int off = 8; off >= 1; off >>= 1)
                rmax = fmaxf(rmax, __shfl_xor_sync(0xffffffffu, rmax, off));
            float mnew = fmaxf(m_i[i], rmax);
            float corr = expf(m_i[i] - mnew);
            float rsum = 0.f;
#pragma unroll
            for (int j = 0; j < 4; j++) {
                s[i][j] = expf(s[i][j] - mnew);
                rsum += s[i][j];
            }
#pragma unroll
            for (int off = 8; off >= 1; off >>= 1)
                rsum += __shfl_xor_sync(0xffffffffu, rsum, off);
            l_i[i] = l_i[i] * corr + rsum;
            m_i[i] = mnew;
#pragma unroll
            for (int j = 0; j < 4; j++) O[i][j] *= corr;
#pragma unroll
            for (int j = 0; j < 4; j++)
                PS(ty + 16 * i, tx + 16 * j) = s[i][j];
        }
        __syncthreads();

        // Phase 2: O += P V
#pragma unroll 8
        for (int jn = 0; jn < 64; jn++) {
            float pv[4], vv[4];
#pragma unroll
            for (int i = 0; i < 4; i++) pv[i] = PS(ty + 16 * i, jn);
#pragma unroll
            for (int j = 0; j < 4; j++) vv[j] = VS(jn, tx + 16 * j);
#pragma unroll
            for (int i = 0; i < 4; i++)
#pragma unroll
                for (int j = 0; j < 4; j++)
                    O[i][j] += pv[i] * vv[j];
        }
        __syncthreads();
    }

    // Epilogue: O /= l, write [b][l][h*64+e]
    const int bb = bh >> 4;
    const int h = bh & 15;
#pragma unroll
    for (int i = 0; i < 4; i++) {
        const int row = qt * 64 + ty + 16 * i;
        const float inv_l = 1.0f / l_i[i];
        size_t base = (size_t)(bb * Lc + row) * Dc + h * Dhc;
#pragma unroll
        for (int j = 0; j < 4; j++)
            g_o[base + tx + 16 * j] = O[i][j] * inv_l;
    }
}

// ---------------------------------------------------------------------------
extern "C" void kernel_launch(void* const* d_in, const int* in_sizes, int n_in,
                              void* d_out, int out_size)
{
    const float* x    = (const float*)d_in[0];
    const float* Wq   = (const float*)d_in[1];
    const float* Wk   = (const float*)d_in[2];
    const float* Wv   = (const float*)d_in[3];
    const float* Wout = (const float*)d_in[4];
    float* out = (float*)d_out;

    cudaFuncSetAttribute(flash_kernel,
                         cudaFuncAttributeMaxDynamicSharedMemorySize, FL_SMEM);

    dim3 g1(Mg / 128, Ng / 128, 3);
    qkv_kernel<<<g1, 256>>>(x, Wq, Wk, Wv);

    dim3 g2(Lc / 64, Bc * Hc);
    flash_kernel<<<g2, 256, FL_SMEM>>>();

    dim3 g3(Mg / 128, Dc / 128);
    out_kernel<<<g3, 256>>>(Wout, out);
}